// round 15
// baseline (speedup 1.0000x reference)
#include <cuda_runtime.h>
#include <cstdint>

#define E_TOTAL   800000
#define D_IN      64
#define D_R       128
#define TILE_E    128
#define NTHREADS  512
#define GRID      148
#define NUM_TILES (E_TOTAL / TILE_E)  // 6250, exact
#define A_STRIDE  132                 // padded fp32 row stride (528B)
#define FST       20                  // warp-filt row stride in words (80B)
#define GROUP_E   32                  // edges per 128-thread group
#define SCALE_FIX 1.000352f           // cancels tf32 truncation bias on A

struct Group {
    float A[2][GROUP_E * A_STRIDE];   // 2 x 16.9 KB (double-buffered)
};
struct Smem {
    Group gr[4];                      // 135.2 KB
    float F[16][GROUP_E * FST];       // per-warp filt staging, 16 x 2.56 KB
    float bias_s[64];
};                                    // ~176.5 KB

// ---------------- helpers ----------------
__device__ __forceinline__ uint32_t smem_u32(const void* p) {
    uint32_t a;
    asm("{ .reg .u64 t; cvta.to.shared.u64 t, %1; cvt.u32.u64 %0, t; }" : "=r"(a) : "l"(p));
    return a;
}
__device__ __forceinline__ void cp_async16(uint32_t saddr, const void* gptr) {
    asm volatile("cp.async.cg.shared.global [%0], [%1], 16;" :: "r"(saddr), "l"(gptr));
}
#define CP_COMMIT() asm volatile("cp.async.commit_group;" ::: "memory")
#define CP_WAIT0()  asm volatile("cp.async.wait_group 0;" ::: "memory")
#define GBAR(id)    asm volatile("bar.sync %0, 128;" :: "r"(id) : "memory")

// ldmatrix x4 .b16 on an 8x8-f32-col-pair view: exact m16n8k8 tf32 A fragment.
__device__ __forceinline__ void ldsm_x4(uint32_t* r, uint32_t addr) {
    asm volatile("ldmatrix.sync.aligned.m8n8.x4.shared.b16 {%0,%1,%2,%3}, [%4];"
                 : "=r"(r[0]), "=r"(r[1]), "=r"(r[2]), "=r"(r[3]) : "r"(addr));
}
__device__ __forceinline__ void mma_tf32(float c[4],
                                         uint32_t a0, uint32_t a1, uint32_t a2, uint32_t a3,
                                         uint32_t b0, uint32_t b1) {
    asm volatile(
        "mma.sync.aligned.m16n8k8.row.col.f32.tf32.tf32.f32 "
        "{%0,%1,%2,%3}, {%4,%5,%6,%7}, {%8,%9}, {%0,%1,%2,%3};"
        : "+f"(c[0]), "+f"(c[1]), "+f"(c[2]), "+f"(c[3])
        : "r"(a0), "r"(a1), "r"(a2), "r"(a3), "r"(b0), "r"(b1));
}
__device__ __forceinline__ uint32_t f2tf32_rna(float f) {
    uint32_t r;
    asm("cvt.rna.tf32.f32 %0, %1;" : "=r"(r) : "f"(f));
    return r;
}
__device__ __forceinline__ void red_add_v4(float* p, float a, float b, float c, float d) {
    asm volatile("red.global.add.v4.f32 [%0], {%1, %2, %3, %4};"
                 :: "l"(p), "f"(a), "f"(b), "f"(c), "f"(d) : "memory");
}

__global__ void zero_out_kernel(float4* out, int n4) {
    int i = blockIdx.x * blockDim.x + threadIdx.x;
    if (i < n4) out[i] = make_float4(0.f, 0.f, 0.f, 0.f);
}

// Group loads its own 32 rows of tile tl: exactly 8 float4s per thread.
__device__ __forceinline__ void issue_group_tile(float* abuf, int tl, int grp, int tid_g,
                                                 const float* __restrict__ eb) {
    const float4* gp = reinterpret_cast<const float4*>(
        eb + ((size_t)tl * TILE_E + grp * GROUP_E) * D_R);
    #pragma unroll
    for (int q = 0; q < 8; q++) {
        int idx = q * 128 + tid_g;          // 0..1023
        int r   = idx >> 5;                 // local row 0..31
        int c4  = idx & 31;
        cp_async16(smem_u32(abuf + r * A_STRIDE + c4 * 4), gp + idx);
    }
}

// ---------------- main fused kernel ----------------
__global__ void __launch_bounds__(NTHREADS, 1)
fused_tf32_warpep(const float* __restrict__ x,
                  const float* __restrict__ eb,
                  const int*   __restrict__ src,
                  const int*   __restrict__ dst,
                  const float* __restrict__ W,
                  const float* __restrict__ bias,
                  float*       __restrict__ out)
{
    extern __shared__ char smem_raw[];
    Smem* s = reinterpret_cast<Smem*>(smem_raw);

    const int tid   = threadIdx.x;
    const int w     = tid >> 5;       // 0..15
    const int lane  = tid & 31;
    const int g     = lane >> 2;      // 0..7
    const int t     = lane & 3;       // 0..3
    const int grp   = tid >> 7;       // 0..3
    const int tid_g = tid & 127;
    const int ng    = (tid >> 5) & 3; // warp-in-group = n group
    const int barid = 1 + grp;

    Group* G = &s->gr[grp];
    float* F = s->F[w];               // this warp's private staging

    // bias -> smem once (broadcast reads at scatter time)
    if (tid < 16)
        reinterpret_cast<float4*>(s->bias_s)[tid] =
            __ldg(reinterpret_cast<const float4*>(bias) + tid);

    // ldmatrix per-lane offset (bytes) within an A buffer
    const int lrow = ((lane >> 3) & 1) * 8 + (lane & 7);
    const uint32_t laneoff = (uint32_t)(lrow * (A_STRIDE * 4) + (lane >> 4) * 16);
    const uint32_t abuf_addr[2] = { smem_u32(G->A[0]), smem_u32(G->A[1]) };

    // ---- W fragments resident in registers (64 regs/thread) ----
    float2 wreg[16][2];
    #pragma unroll
    for (int ks = 0; ks < 16; ks++) {
        #pragma unroll
        for (int j = 0; j < 2; j++) {
            int n = ng * 16 + j * 8 + g;
            int k = ks * 8 + t;
            wreg[ks][j].x = __uint_as_float(f2tf32_rna(__ldg(W + n * D_R + k)));
            wreg[ks][j].y = __uint_as_float(f2tf32_rna(__ldg(W + n * D_R + k + 4)));
        }
    }
    __syncthreads();                  // bias_s visible to all groups

    const int bid     = blockIdx.x;
    const int n_tiles = (NUM_TILES - bid + GRID - 1) / GRID;

    // ---- prologue: group prefetches its slice of tile 0 ----
    issue_group_tile(G->A[0], bid, grp, tid_g, eb);
    CP_COMMIT();

    for (int i = 0; i < n_tiles; i++) {
        CP_WAIT0();                 // this group's tile i slice resident
        GBAR(barid);                // publish A[i&1]; all 4 warps finished
                                    // iter i-1's MMA -> A[(i+1)&1] free

        // ---- prefetch tile i+1 slice ----
        if (i + 1 < n_tiles) {
            issue_group_tile(G->A[(i + 1) & 1], bid + (i + 1) * GRID, grp, tid_g, eb);
            CP_COMMIT();
        }

        const uint32_t abase = abuf_addr[i & 1] + laneoff;
        const int tl = bid + i * GRID;

        // ---- MMA: warp = 32 edges x 16 n (identical to R9) ----
        float c[2][2][4];
        #pragma unroll
        for (int m = 0; m < 2; m++)
            #pragma unroll
            for (int j = 0; j < 2; j++)
                { c[m][j][0] = 0.f; c[m][j][1] = 0.f; c[m][j][2] = 0.f; c[m][j][3] = 0.f; }

        #pragma unroll
        for (int ks = 0; ks < 16; ks++) {
            #pragma unroll
            for (int m = 0; m < 2; m++) {
                uint32_t fa[4];
                ldsm_x4(fa, abase + (uint32_t)(m * 16 * (A_STRIDE * 4) + ks * 32));
                #pragma unroll
                for (int j = 0; j < 2; j++)
                    mma_tf32(c[m][j], fa[0], fa[1], fa[2], fa[3],
                             __float_as_uint(wreg[ks][j].x),
                             __float_as_uint(wreg[ks][j].y));
            }
        }

        // ---- stage C into WARP-PRIVATE filt (rows = local edge, 16 cols) ----
        #pragma unroll
        for (int m = 0; m < 2; m++) {
            #pragma unroll
            for (int j = 0; j < 2; j++) {
                *reinterpret_cast<float2*>(F + (m * 16 + g) * FST + j * 8 + 2 * t) =
                    make_float2(c[m][j][0], c[m][j][1]);
                *reinterpret_cast<float2*>(F + (m * 16 + g + 8) * FST + j * 8 + 2 * t) =
                    make_float2(c[m][j][2], c[m][j][3]);
            }
        }
        __syncwarp();               // warp-local staging visible

        // ---- scatter: lane owns edge `lane`, warp's 16-n slice, 4x RED.128 ----
        const int ebase = tl * TILE_E + grp * GROUP_E;
        const int sn = __ldg(src + ebase + lane);
        const int dn = __ldg(dst + ebase + lane);
        const float* xr = x + (size_t)sn * D_IN + ng * 16;
        float*       orow = out + (size_t)dn * D_IN + ng * 16;
        const float* brow = s->bias_s + ng * 16;
        #pragma unroll
        for (int q = 0; q < 4; q++) {
            float4 f  = *reinterpret_cast<const float4*>(F + lane * FST + q * 4);
            float4 bv = *reinterpret_cast<const float4*>(brow + q * 4);  // broadcast
            float4 xv = __ldg(reinterpret_cast<const float4*>(xr + q * 4));
            red_add_v4(orow + q * 4,
                       fmaf(f.x, SCALE_FIX, bv.x) * xv.x,
                       fmaf(f.y, SCALE_FIX, bv.y) * xv.y,
                       fmaf(f.z, SCALE_FIX, bv.z) * xv.z,
                       fmaf(f.w, SCALE_FIX, bv.w) * xv.w);
        }
        __syncwarp();               // F reads done before next tile's staging
        // A[(i+1)&1] overwrite safety comes from next iteration's top GBAR.
    }
}

extern "C" void kernel_launch(void* const* d_in, const int* in_sizes, int n_in,
                              void* d_out, int out_size) {
    const float* x    = (const float*)d_in[0];
    const float* eb   = (const float*)d_in[1];
    const int*   src  = (const int*)d_in[2];
    const int*   dst  = (const int*)d_in[3];
    const float* W    = (const float*)d_in[4];
    const float* bias = (const float*)d_in[5];
    float* out = (float*)d_out;

    int n4 = out_size / 4;
    zero_out_kernel<<<(n4 + 255) / 256, 256>>>((float4*)out, n4);

    cudaFuncSetAttribute(fused_tf32_warpep,
                         cudaFuncAttributeMaxDynamicSharedMemorySize,
                         (int)sizeof(Smem));
    fused_tf32_warpep<<<GRID, NTHREADS, sizeof(Smem)>>>(x, eb, src, dst, W, bias, out);
}

// round 16
// speedup vs baseline: 1.4611x; 1.4611x over previous
#include <cuda_runtime.h>
#include <cstdint>

#define E_TOTAL   800000
#define D_IN      64
#define D_R       128
#define TILE_E    128
#define NTHREADS  512
#define GRID      148
#define NUM_TILES (E_TOTAL / TILE_E)  // 6250, exact
#define A_STRIDE  132                 // padded fp32 row stride (528B)
#define C_STRIDE  68                  // padded filt stride (272B)
#define GROUP_E   32                  // edges per 128-thread group
#define SCALE_FIX 1.000352f           // cancels tf32 truncation bias on A

struct Group {
    float A[2][GROUP_E * A_STRIDE];   // 2 x 16.9 KB (double-buffered)
    float filt[GROUP_E * C_STRIDE];   // 8.7 KB
};
struct Smem { Group gr[4]; };         // ~169 KB

// ---------------- helpers ----------------
__device__ __forceinline__ uint32_t smem_u32(const void* p) {
    uint32_t a;
    asm("{ .reg .u64 t; cvta.to.shared.u64 t, %1; cvt.u32.u64 %0, t; }" : "=r"(a) : "l"(p));
    return a;
}
__device__ __forceinline__ void cp_async16(uint32_t saddr, const void* gptr) {
    asm volatile("cp.async.cg.shared.global [%0], [%1], 16;" :: "r"(saddr), "l"(gptr));
}
#define CP_COMMIT() asm volatile("cp.async.commit_group;" ::: "memory")
#define CP_WAIT0()  asm volatile("cp.async.wait_group 0;" ::: "memory")
#define GBAR(id)    asm volatile("bar.sync %0, 128;" :: "r"(id) : "memory")

__device__ __forceinline__ void prefetch_l1(const void* p) {
    asm volatile("prefetch.global.L1 [%0];" :: "l"(p));
}

// ldmatrix x4 .b16 on an 8x8-f32-col-pair view: exact m16n8k8 tf32 A fragment.
__device__ __forceinline__ void ldsm_x4(uint32_t* r, uint32_t addr) {
    asm volatile("ldmatrix.sync.aligned.m8n8.x4.shared.b16 {%0,%1,%2,%3}, [%4];"
                 : "=r"(r[0]), "=r"(r[1]), "=r"(r[2]), "=r"(r[3]) : "r"(addr));
}
__device__ __forceinline__ void mma_tf32(float c[4],
                                         uint32_t a0, uint32_t a1, uint32_t a2, uint32_t a3,
                                         uint32_t b0, uint32_t b1) {
    asm volatile(
        "mma.sync.aligned.m16n8k8.row.col.f32.tf32.tf32.f32 "
        "{%0,%1,%2,%3}, {%4,%5,%6,%7}, {%8,%9}, {%0,%1,%2,%3};"
        : "+f"(c[0]), "+f"(c[1]), "+f"(c[2]), "+f"(c[3])
        : "r"(a0), "r"(a1), "r"(a2), "r"(a3), "r"(b0), "r"(b1));
}
__device__ __forceinline__ uint32_t f2tf32_rna(float f) {
    uint32_t r;
    asm("cvt.rna.tf32.f32 %0, %1;" : "=r"(r) : "f"(f));
    return r;
}
__device__ __forceinline__ void red_add_v4(float* p, float a, float b, float c, float d) {
    asm volatile("red.global.add.v4.f32 [%0], {%1, %2, %3, %4};"
                 :: "l"(p), "f"(a), "f"(b), "f"(c), "f"(d) : "memory");
}

__global__ void zero_out_kernel(float4* out, int n4) {
    int i = blockIdx.x * blockDim.x + threadIdx.x;
    if (i < n4) out[i] = make_float4(0.f, 0.f, 0.f, 0.f);
}

// Group loads its own 32 rows of tile tl: exactly 8 float4s per thread.
__device__ __forceinline__ void issue_group_tile(float* abuf, int tl, int grp, int tid_g,
                                                 const float* __restrict__ eb) {
    const float4* gp = reinterpret_cast<const float4*>(
        eb + ((size_t)tl * TILE_E + grp * GROUP_E) * D_R);
    #pragma unroll
    for (int q = 0; q < 8; q++) {
        int idx = q * 128 + tid_g;          // 0..1023
        int r   = idx >> 5;                 // local row 0..31
        int c4  = idx & 31;
        cp_async16(smem_u32(abuf + r * A_STRIDE + c4 * 4), gp + idx);
    }
}

// ---------------- main fused kernel ----------------
__global__ void __launch_bounds__(NTHREADS, 1)
fused_tf32_pf(const float* __restrict__ x,
              const float* __restrict__ eb,
              const int*   __restrict__ src,
              const int*   __restrict__ dst,
              const float* __restrict__ W,
              const float* __restrict__ bias,
              float*       __restrict__ out)
{
    extern __shared__ char smem_raw[];
    Smem* s = reinterpret_cast<Smem*>(smem_raw);

    const int tid   = threadIdx.x;
    const int lane  = tid & 31;
    const int g     = lane >> 2;      // 0..7
    const int t     = lane & 3;       // 0..3
    const int grp   = tid >> 7;       // 0..3
    const int tid_g = tid & 127;
    const int ng    = (tid >> 5) & 3; // warp-in-group = n group
    const int barid = 1 + grp;
    const int eL    = tid_g >> 4;     // scatter base edge (0..7)
    const int d4    = tid_g & 15;

    Group* G = &s->gr[grp];

    // ldmatrix per-lane offset (bytes) within an A buffer
    const int lrow = ((lane >> 3) & 1) * 8 + (lane & 7);
    const uint32_t laneoff = (uint32_t)(lrow * (A_STRIDE * 4) + (lane >> 4) * 16);
    const uint32_t abuf_addr[2] = { smem_u32(G->A[0]), smem_u32(G->A[1]) };

    // ---- W fragments resident in registers (64 regs/thread) ----
    float2 wreg[16][2];
    #pragma unroll
    for (int ks = 0; ks < 16; ks++) {
        #pragma unroll
        for (int j = 0; j < 2; j++) {
            int n = ng * 16 + j * 8 + g;
            int k = ks * 8 + t;
            wreg[ks][j].x = __uint_as_float(f2tf32_rna(__ldg(W + n * D_R + k)));
            wreg[ks][j].y = __uint_as_float(f2tf32_rna(__ldg(W + n * D_R + k + 4)));
        }
    }
    const float4 bvec = __ldg(reinterpret_cast<const float4*>(bias) + d4);

    const int bid     = blockIdx.x;
    const int n_tiles = (NUM_TILES - bid + GRID - 1) / GRID;

    // ---- prologue: group prefetches its slice of tile 0 ----
    issue_group_tile(G->A[0], bid, grp, tid_g, eb);
    CP_COMMIT();

    for (int i = 0; i < n_tiles; i++) {
        CP_WAIT0();                 // this group's tile i slice resident
        GBAR(barid);                // publish A[i&1]; group finished iter i-1

        // ---- prefetch tile i+1 slice (overlaps MMA + epilogue below) ----
        if (i + 1 < n_tiles) {
            issue_group_tile(G->A[(i + 1) & 1], bid + (i + 1) * GRID, grp, tid_g, eb);
            CP_COMMIT();
        }

        const uint32_t abase = abuf_addr[i & 1] + laneoff;
        const int tl    = bid + i * GRID;
        const int ebase = tl * TILE_E + grp * GROUP_E;

        // ---- NEW: preload src indices + L1-prefetch gather targets ----
        int snr[4];
        #pragma unroll
        for (int r = 0; r < 4; r++)
            snr[r] = __ldg(src + ebase + eL + 8 * r);
        #pragma unroll
        for (int r = 0; r < 4; r++)
            prefetch_l1(x + (size_t)snr[r] * D_IN + d4 * 4);
        if (tid_g < 8) prefetch_l1(dst + ebase + tid_g * 4);

        // ---- MMA: warp = 32 edges x 16 n, W from registers (as R9) ----
        float c[2][2][4];
        #pragma unroll
        for (int m = 0; m < 2; m++)
            #pragma unroll
            for (int j = 0; j < 2; j++)
                { c[m][j][0] = 0.f; c[m][j][1] = 0.f; c[m][j][2] = 0.f; c[m][j][3] = 0.f; }

        #pragma unroll
        for (int ks = 0; ks < 16; ks++) {
            #pragma unroll
            for (int m = 0; m < 2; m++) {
                uint32_t fa[4];
                ldsm_x4(fa, abase + (uint32_t)(m * 16 * (A_STRIDE * 4) + ks * 32));
                #pragma unroll
                for (int j = 0; j < 2; j++)
                    mma_tf32(c[m][j], fa[0], fa[1], fa[2], fa[3],
                             __float_as_uint(wreg[ks][j].x),
                             __float_as_uint(wreg[ks][j].y));
            }
        }

        // ---- stage C into group's filt (as R9) ----
        #pragma unroll
        for (int m = 0; m < 2; m++) {
            float* fr = G->filt + (m * 16 + g) * C_STRIDE + ng * 16;
            #pragma unroll
            for (int j = 0; j < 2; j++) {
                *reinterpret_cast<float2*>(fr + j * 8 + 2 * t) =
                    make_float2(c[m][j][0], c[m][j][1]);
                *reinterpret_cast<float2*>(fr + 8 * C_STRIDE + j * 8 + 2 * t) =
                    make_float2(c[m][j][2], c[m][j][3]);
            }
        }
        GBAR(barid);                // group's filt complete

        // ---- scatter: 4 v4-chunks per thread; x rows should be L1-hot ----
        #pragma unroll
        for (int rep = 0; rep < 4; rep++) {
            int e_loc = eL + 8 * rep;             // 0..31
            float4 f = *reinterpret_cast<const float4*>(G->filt + e_loc * C_STRIDE + d4 * 4);
            int dn = __ldg(dst + ebase + e_loc);
            float4 xv = __ldg(reinterpret_cast<const float4*>(
                                  x + (size_t)snr[rep] * D_IN) + d4);
            red_add_v4(out + (size_t)dn * D_IN + d4 * 4,
                       fmaf(f.x, SCALE_FIX, bvec.x) * xv.x,
                       fmaf(f.y, SCALE_FIX, bvec.y) * xv.y,
                       fmaf(f.z, SCALE_FIX, bvec.z) * xv.z,
                       fmaf(f.w, SCALE_FIX, bvec.w) * xv.w);
        }
        // Next iteration's top GBAR (after CP_WAIT0) orders this scatter's
        // filt reads before the next staging writes; the A[(i+1)&1] overwrite
        // was ordered by this iteration's top GBAR.
    }
}

extern "C" void kernel_launch(void* const* d_in, const int* in_sizes, int n_in,
                              void* d_out, int out_size) {
    const float* x    = (const float*)d_in[0];
    const float* eb   = (const float*)d_in[1];
    const int*   src  = (const int*)d_in[2];
    const int*   dst  = (const int*)d_in[3];
    const float* W    = (const float*)d_in[4];
    const float* bias = (const float*)d_in[5];
    float* out = (float*)d_out;

    int n4 = out_size / 4;
    zero_out_kernel<<<(n4 + 255) / 256, 256>>>((float4*)out, n4);

    cudaFuncSetAttribute(fused_tf32_pf,
                         cudaFuncAttributeMaxDynamicSharedMemorySize,
                         (int)sizeof(Smem));
    fused_tf32_pf<<<GRID, NTHREADS, sizeof(Smem)>>>(x, eb, src, dst, W, bias, out);
}

// round 17
// speedup vs baseline: 1.4816x; 1.0141x over previous
#include <cuda_runtime.h>
#include <cstdint>

#define E_TOTAL   800000
#define D_IN      64
#define D_R       128
#define GTILE_E   32                  // edges per group-tile (steal unit)
#define NT_TILES  (E_TOTAL / GTILE_E) // 25000, exact
#define NTHREADS  512
#define GRID      148
#define A_STRIDE  132                 // padded fp32 row stride (528B)
#define C_STRIDE  68                  // padded filt stride (272B)
#define SCALE_FIX 1.000352f           // cancels tf32 truncation bias on A

__device__ int g_ctr;                 // work-stealing counter (reset by zero_out)

struct Group {
    float A[2][GTILE_E * A_STRIDE];   // 2 x 16.9 KB (double-buffered)
    float filt[GTILE_E * C_STRIDE];   // 8.7 KB
    int   t_slot[2];                  // stolen tile ids (parity double-buffer)
    int   pad[2];
};
struct Smem { Group gr[4]; };         // ~169 KB

// ---------------- helpers ----------------
__device__ __forceinline__ uint32_t smem_u32(const void* p) {
    uint32_t a;
    asm("{ .reg .u64 t; cvta.to.shared.u64 t, %1; cvt.u32.u64 %0, t; }" : "=r"(a) : "l"(p));
    return a;
}
__device__ __forceinline__ void cp_async16(uint32_t saddr, const void* gptr) {
    asm volatile("cp.async.cg.shared.global [%0], [%1], 16;" :: "r"(saddr), "l"(gptr));
}
#define CP_COMMIT() asm volatile("cp.async.commit_group;" ::: "memory")
#define CP_WAIT0()  asm volatile("cp.async.wait_group 0;" ::: "memory")
#define GBAR(id)    asm volatile("bar.sync %0, 128;" :: "r"(id) : "memory")

// ldmatrix x4 .b16 on an 8x8-f32-col-pair view: exact m16n8k8 tf32 A fragment.
__device__ __forceinline__ void ldsm_x4(uint32_t* r, uint32_t addr) {
    asm volatile("ldmatrix.sync.aligned.m8n8.x4.shared.b16 {%0,%1,%2,%3}, [%4];"
                 : "=r"(r[0]), "=r"(r[1]), "=r"(r[2]), "=r"(r[3]) : "r"(addr));
}
__device__ __forceinline__ void mma_tf32(float c[4],
                                         uint32_t a0, uint32_t a1, uint32_t a2, uint32_t a3,
                                         uint32_t b0, uint32_t b1) {
    asm volatile(
        "mma.sync.aligned.m16n8k8.row.col.f32.tf32.tf32.f32 "
        "{%0,%1,%2,%3}, {%4,%5,%6,%7}, {%8,%9}, {%0,%1,%2,%3};"
        : "+f"(c[0]), "+f"(c[1]), "+f"(c[2]), "+f"(c[3])
        : "r"(a0), "r"(a1), "r"(a2), "r"(a3), "r"(b0), "r"(b1));
}
__device__ __forceinline__ uint32_t f2tf32_rna(float f) {
    uint32_t r;
    asm("cvt.rna.tf32.f32 %0, %1;" : "=r"(r) : "f"(f));
    return r;
}
__device__ __forceinline__ void red_add_v4(float* p, float a, float b, float c, float d) {
    asm volatile("red.global.add.v4.f32 [%0], {%1, %2, %3, %4};"
                 :: "l"(p), "f"(a), "f"(b), "f"(c), "f"(d) : "memory");
}

__global__ void zero_out_kernel(float4* out, int n4) {
    int i = blockIdx.x * blockDim.x + threadIdx.x;
    if (i == 0) g_ctr = 0;            // reset steal counter every launch/replay
    if (i < n4) out[i] = make_float4(0.f, 0.f, 0.f, 0.f);
}

// Group loads its 32-edge tile tl: exactly 8 float4s per thread.
__device__ __forceinline__ void issue_group_tile(float* abuf, int tl, int tid_g,
                                                 const float* __restrict__ eb) {
    const float4* gp = reinterpret_cast<const float4*>(
        eb + (size_t)tl * (GTILE_E * D_R));
    #pragma unroll
    for (int q = 0; q < 8; q++) {
        int idx = q * 128 + tid_g;          // 0..1023
        int r   = idx >> 5;                 // local row 0..31
        int c4  = idx & 31;
        cp_async16(smem_u32(abuf + r * A_STRIDE + c4 * 4), gp + idx);
    }
}

// ---------------- main fused kernel ----------------
__global__ void __launch_bounds__(NTHREADS, 1)
fused_tf32_steal(const float* __restrict__ x,
                 const float* __restrict__ eb,
                 const int*   __restrict__ src,
                 const int*   __restrict__ dst,
                 const float* __restrict__ W,
                 const float* __restrict__ bias,
                 float*       __restrict__ out)
{
    extern __shared__ char smem_raw[];
    Smem* s = reinterpret_cast<Smem*>(smem_raw);

    const int tid   = threadIdx.x;
    const int lane  = tid & 31;
    const int g     = lane >> 2;      // 0..7
    const int t     = lane & 3;       // 0..3
    const int grp   = tid >> 7;       // 0..3
    const int tid_g = tid & 127;
    const int ng    = (tid >> 5) & 3; // warp-in-group = n group
    const int barid = 1 + grp;
    const int eL    = tid_g >> 4;     // scatter base edge (0..7)
    const int d4    = tid_g & 15;

    Group* G = &s->gr[grp];

    // ldmatrix per-lane offset (bytes) within an A buffer
    const int lrow = ((lane >> 3) & 1) * 8 + (lane & 7);
    const uint32_t laneoff = (uint32_t)(lrow * (A_STRIDE * 4) + (lane >> 4) * 16);
    const uint32_t abuf_addr[2] = { smem_u32(G->A[0]), smem_u32(G->A[1]) };

    // ---- W fragments resident in registers (64 regs/thread) ----
    float2 wreg[16][2];
    #pragma unroll
    for (int ks = 0; ks < 16; ks++) {
        #pragma unroll
        for (int j = 0; j < 2; j++) {
            int n = ng * 16 + j * 8 + g;
            int k = ks * 8 + t;
            wreg[ks][j].x = __uint_as_float(f2tf32_rna(__ldg(W + n * D_R + k)));
            wreg[ks][j].y = __uint_as_float(f2tf32_rna(__ldg(W + n * D_R + k + 4)));
        }
    }
    const float4 bvec = __ldg(reinterpret_cast<const float4*>(bias) + d4);

    // ---- prologue: steal first tile, prefetch it, steal second ----
    if (tid_g == 0) G->t_slot[0] = atomicAdd(&g_ctr, 1);
    GBAR(barid);
    int t_cur = G->t_slot[0];                 // < NT_TILES (592 groups)
    issue_group_tile(G->A[0], t_cur, tid_g, eb);
    CP_COMMIT();
    if (tid_g == 0) G->t_slot[1] = atomicAdd(&g_ctr, 1);

    int buf = 0, par = 1;
    while (t_cur < NT_TILES) {
        CP_WAIT0();                 // A[buf] (tile t_cur) resident
        GBAR(barid);                // publish A[buf] + t_slot[par]; group done
                                    // with iter-1 (filt + A[buf^1] free)

        const int t_next = G->t_slot[par];

        // ---- prefetch stolen tile t_next; steal one more for next iter ----
        if (t_next < NT_TILES)
            issue_group_tile(G->A[buf ^ 1], t_next, tid_g, eb);
        CP_COMMIT();                // unconditional: group accounting fixed
        if (tid_g == 0 && t_next < NT_TILES)
            G->t_slot[par ^ 1] = atomicAdd(&g_ctr, 1);
        // t_slot[par^1] was last read before THIS GBAR; next read after next GBAR.

        // ---- MMA: warp = 32 edges x 16 n (identical to R9) ----
        const uint32_t abase = abuf_addr[buf] + laneoff;
        float c[2][2][4];
        #pragma unroll
        for (int m = 0; m < 2; m++)
            #pragma unroll
            for (int j = 0; j < 2; j++)
                { c[m][j][0] = 0.f; c[m][j][1] = 0.f; c[m][j][2] = 0.f; c[m][j][3] = 0.f; }

        #pragma unroll
        for (int ks = 0; ks < 16; ks++) {
            #pragma unroll
            for (int m = 0; m < 2; m++) {
                uint32_t fa[4];
                ldsm_x4(fa, abase + (uint32_t)(m * 16 * (A_STRIDE * 4) + ks * 32));
                #pragma unroll
                for (int j = 0; j < 2; j++)
                    mma_tf32(c[m][j], fa[0], fa[1], fa[2], fa[3],
                             __float_as_uint(wreg[ks][j].x),
                             __float_as_uint(wreg[ks][j].y));
            }
        }

        // ---- stage C into group's filt (identical to R9) ----
        #pragma unroll
        for (int m = 0; m < 2; m++) {
            float* fr = G->filt + (m * 16 + g) * C_STRIDE + ng * 16;
            #pragma unroll
            for (int j = 0; j < 2; j++) {
                *reinterpret_cast<float2*>(fr + j * 8 + 2 * t) =
                    make_float2(c[m][j][0], c[m][j][1]);
                *reinterpret_cast<float2*>(fr + 8 * C_STRIDE + j * 8 + 2 * t) =
                    make_float2(c[m][j][2], c[m][j][3]);
            }
        }
        GBAR(barid);                // group's filt complete

        // ---- scatter: 4 v4-chunks per thread (identical to R9) ----
        const int ebase = t_cur * GTILE_E;
        #pragma unroll
        for (int rep = 0; rep < 4; rep++) {
            int e_loc = eL + 8 * rep;             // 0..31
            float4 f = *reinterpret_cast<const float4*>(G->filt + e_loc * C_STRIDE + d4 * 4);
            int sn = __ldg(src + ebase + e_loc);
            int dn = __ldg(dst + ebase + e_loc);
            float4 xv = __ldg(reinterpret_cast<const float4*>(x + (size_t)sn * D_IN) + d4);
            red_add_v4(out + (size_t)dn * D_IN + d4 * 4,
                       fmaf(f.x, SCALE_FIX, bvec.x) * xv.x,
                       fmaf(f.y, SCALE_FIX, bvec.y) * xv.y,
                       fmaf(f.z, SCALE_FIX, bvec.z) * xv.z,
                       fmaf(f.w, SCALE_FIX, bvec.w) * xv.w);
        }

        t_cur = t_next;
        buf ^= 1;
        par ^= 1;
        // Next iteration's top GBAR (after CP_WAIT0) orders this scatter's
        // filt reads before the next staging writes; the A[buf^1] overwrite
        // was ordered by this iteration's top GBAR.
    }
}

extern "C" void kernel_launch(void* const* d_in, const int* in_sizes, int n_in,
                              void* d_out, int out_size) {
    const float* x    = (const float*)d_in[0];
    const float* eb   = (const float*)d_in[1];
    const int*   src  = (const int*)d_in[2];
    const int*   dst  = (const int*)d_in[3];
    const float* W    = (const float*)d_in[4];
    const float* bias = (const float*)d_in[5];
    float* out = (float*)d_out;

    int n4 = out_size / 4;
    zero_out_kernel<<<(n4 + 255) / 256, 256>>>((float4*)out, n4);

    cudaFuncSetAttribute(fused_tf32_steal,
                         cudaFuncAttributeMaxDynamicSharedMemorySize,
                         (int)sizeof(Smem));
    fused_tf32_steal<<<GRID, NTHREADS, sizeof(Smem)>>>(x, eb, src, dst, W, bias, out);
}